// round 8
// baseline (speedup 1.0000x reference)
#include <cuda_runtime.h>
#include <cstdint>

#define BB   2048
#define TT   1024
#define NW   8            // warps per CTA
#define RPC  2            // batch rows per CTA
#define GRID (BB / RPC)
#define CPR  8            // chunks (stages) per row per warp
#define NCHK (RPC * CPR)  // total chunks per warp

__device__ __forceinline__ uint32_t s2u(const void* p) {
    return (uint32_t)__cvta_generic_to_shared(p);
}

// ============================ Fused decoder ================================
// One CTA (256 threads) per RPC batch rows. Each warp owns 128 consecutive
// z rows of the current batch row, streamed through a private 2-slot cp.async
// ring (2KB chunks / 16 rows, XOR-swizzled). The chunk pipeline runs on a
// GLOBAL counter across the row boundary, so row i+1's loads are in flight
// while row i's scan (phase B) executes -> no DRAM demand dip between phases.
__global__ __launch_bounds__(256, 4)
void fused_decoder_kernel(const float* __restrict__ init_states,
                          const float* __restrict__ z,
                          const float* __restrict__ W,
                          float* __restrict__ out) {
    __shared__ alignas(16) float4 zring[NW][2][128];  // 32KB per-warp rings
    __shared__ alignas(16) float2 sv[2][TT];          // 16KB double-buffered vectors
    __shared__ float2 agg[8];
    __shared__ float  sPW[5][4];
    __shared__ float4 sW0[8], sW1[8];

    const int b0   = blockIdx.x * RPC;
    const int tid  = threadIdx.x;
    const int lane = tid & 31;
    const int warp = tid >> 5;

    if (tid < 64) {
        const int rr = tid >> 5, c = tid & 31;
        reinterpret_cast<float*>(rr ? sW1 : sW0)[c] = W[rr * 34 + 2 + c];
    }

    // ---- precomputed swizzled offsets (lane-only) ----
    int woff[4], roff[4];
    #pragma unroll
    for (int k = 0; k < 4; ++k) {
        const int i2 = lane + 32 * k;
        const int row = i2 >> 3, j = i2 & 7;
        woff[k] = row * 8 + ((j + row) & 7);
    }
    const int rrow = lane >> 1;
    const int half = (lane & 1) * 4;
    #pragma unroll
    for (int k = 0; k < 4; ++k) {
        const int c = half + k;
        roff[k] = rrow * 8 + ((c + rrow) & 7);
    }

    const float4* z4 = reinterpret_cast<const float4*>(z);
    const uint32_t slotu[2] = { s2u(&zring[warp][0][0]), s2u(&zring[warp][1][0]) };

    // global chunk c: row = c/8, stage = c%8, slot = c&1
    auto issue = [&](int c) {
        const int row = c >> 3, st = c & 7;
        const float4* src = z4 + ((size_t)(b0 + row) * TT + warp * 128) * 8
                               + st * 128 + lane;
        const uint32_t dst = slotu[c & 1];
        #pragma unroll
        for (int k = 0; k < 4; ++k) {
            asm volatile("cp.async.cg.shared.global [%0], [%1], 16;"
                         :: "r"(dst + (uint32_t)woff[k] * 16u), "l"(src + 32 * k));
        }
    };

    issue(0);
    asm volatile("cp.async.commit_group;" ::: "memory");
    issue(1);
    asm volatile("cp.async.commit_group;" ::: "memory");

    __syncthreads();                           // publish sW0/sW1

    const float a00 = __ldg(&W[0]),  a01 = __ldg(&W[1]);
    const float a10 = __ldg(&W[34]), a11 = __ldg(&W[35]);

    for (int row = 0; row < RPC; ++row) {
        const int buf = row & 1;

        // ---------------- Phase A: 8 pipelined chunks ----------------
        #pragma unroll 1
        for (int s = 0; s < CPR; ++s) {
            asm volatile("cp.async.wait_group 1;" ::: "memory");
            __syncwarp();
            const float4* slot = &zring[warp][(row * CPR + s) & 1][0];

            float px = 0.f, py = 0.f;
            #pragma unroll
            for (int k = 0; k < 4; ++k) {
                const float4 q  = slot[roff[k]];
                const float4 w0 = sW0[half + k];
                const float4 w1 = sW1[half + k];
                px = fmaf(q.x, w0.x, fmaf(q.y, w0.y, fmaf(q.z, w0.z, fmaf(q.w, w0.w, px))));
                py = fmaf(q.x, w1.x, fmaf(q.y, w1.y, fmaf(q.z, w1.z, fmaf(q.w, w1.w, py))));
            }
            float u  = (lane & 1) ? py : px;
            float w_ = (lane & 1) ? px : py;
            u += __shfl_xor_sync(0xffffffffu, w_, 1);
            const float pv = __shfl_xor_sync(0xffffffffu, u, 1);
            const int r = warp * 128 + s * 16 + rrow;
            if (!(lane & 1) && r + 1 < TT) sv[buf][r + 1] = make_float2(u, pv);

            __syncwarp();
            const int c = row * CPR + s;
            if (c + 2 < NCHK) issue(c + 2);    // crosses the row boundary
            asm volatile("cp.async.commit_group;" ::: "memory");
        }
        if (tid == 0)
            sv[buf][0] = make_float2(init_states[2 * (b0 + row)],
                                     init_states[2 * (b0 + row) + 1]);
        __syncthreads();                       // sv[buf] complete; agg reuse ordered

        // ---------------- Phase B: chunked affine scan ----------------
        float4* svp = reinterpret_cast<float4*>(sv[buf]) + tid * 2;

        float2 s2;
        {
            const float4 c0 = svp[0], c1 = svp[1];
            s2 = make_float2(c0.x, c0.y);
            float s1x = fmaf(a00, s2.x, fmaf(a01, s2.y, c0.z));
            float s1y = fmaf(a10, s2.x, fmaf(a11, s2.y, c0.w));
            float s2x = fmaf(a00, s1x, fmaf(a01, s1y, c1.x));
            float s2y = fmaf(a10, s1x, fmaf(a11, s1y, c1.y));
            float s3x = fmaf(a00, s2x, fmaf(a01, s2y, c1.z));
            float s3y = fmaf(a10, s2x, fmaf(a11, s2y, c1.w));
            svp[0] = make_float4(s2.x, s2.y, s1x, s1y);
            svp[1] = make_float4(s2x, s2y, s3x, s3y);
            s2 = make_float2(s3x, s3y);
        }

        float p00 = a00, p01 = a01, p10 = a10, p11 = a11;
        #pragma unroll
        for (int i = 0; i < 2; ++i) {
            float q00 = p00*p00 + p01*p10, q01 = p00*p01 + p01*p11;
            float q10 = p10*p00 + p11*p10, q11 = p10*p01 + p11*p11;
            p00 = q00; p01 = q01; p10 = q10; p11 = q11;
        }

        float2 x = s2;
        #pragma unroll
        for (int d = 0; d < 5; ++d) {
            if (tid == 0) { sPW[d][0]=p00; sPW[d][1]=p01; sPW[d][2]=p10; sPW[d][3]=p11; }
            const int o = 1 << d;
            float ox = __shfl_up_sync(0xffffffffu, x.x, o);
            float oy = __shfl_up_sync(0xffffffffu, x.y, o);
            if (lane >= o) {
                x.x = fmaf(p00, ox, fmaf(p01, oy, x.x));
                x.y = fmaf(p10, ox, fmaf(p11, oy, x.y));
            }
            float q00 = p00*p00 + p01*p10, q01 = p00*p01 + p01*p11;
            float q10 = p10*p00 + p11*p10, q11 = p10*p01 + p11*p11;
            p00 = q00; p01 = q01; p10 = q10; p11 = q11;
        }

        if (lane == 31) agg[warp] = x;
        __syncthreads();

        float2 P = make_float2(0.f, 0.f);
        for (int u = 0; u < warp; ++u) {
            float nx = fmaf(p00, P.x, fmaf(p01, P.y, agg[u].x));
            float ny = fmaf(p10, P.x, fmaf(p11, P.y, agg[u].y));
            P.x = nx; P.y = ny;
        }

        float Ex = __shfl_up_sync(0xffffffffu, x.x, 1);
        float Ey = __shfl_up_sync(0xffffffffu, x.y, 1);
        if (lane == 0) { Ex = 0.f; Ey = 0.f; }

        float m00 = 1.f, m01 = 0.f, m10 = 0.f, m11 = 1.f;
        #pragma unroll
        for (int d = 0; d < 5; ++d) {
            if (lane & (1 << d)) {
                const float v0 = sPW[d][0], v1 = sPW[d][1];
                const float v2 = sPW[d][2], v3 = sPW[d][3];
                float n00 = v0*m00 + v1*m10, n01 = v0*m01 + v1*m11;
                float n10 = v2*m00 + v3*m10, n11 = v2*m01 + v3*m11;
                m00 = n00; m01 = n01; m10 = n10; m11 = n11;
            }
        }
        const float bx = Ex + m00 * P.x + m01 * P.y;
        const float by = Ey + m10 * P.x + m11 * P.y;

        float cx = fmaf(a00, bx, a01 * by);
        float cy = fmaf(a10, bx, a11 * by);
        const float4 r0 = svp[0], r1 = svp[1];
        float4 o0, o1;
        o0.x = r0.x + cx;  o0.y = r0.y + cy;
        { float nx = fmaf(a00, cx, a01 * cy), ny = fmaf(a10, cx, a11 * cy); cx = nx; cy = ny; }
        o0.z = r0.z + cx;  o0.w = r0.w + cy;
        { float nx = fmaf(a00, cx, a01 * cy), ny = fmaf(a10, cx, a11 * cy); cx = nx; cy = ny; }
        o1.x = r1.x + cx;  o1.y = r1.y + cy;
        { float nx = fmaf(a00, cx, a01 * cy), ny = fmaf(a10, cx, a11 * cy); cx = nx; cy = ny; }
        o1.z = r1.z + cx;  o1.w = r1.w + cy;

        float4* op = reinterpret_cast<float4*>(out)
                     + ((size_t)(b0 + row) * TT / 2) + tid * 2;
        __stcs(op,     o0);
        __stcs(op + 1, o1);
    }
}

extern "C" void kernel_launch(void* const* d_in, const int* in_sizes, int n_in,
                              void* d_out, int out_size) {
    const float* init_states = (const float*)d_in[0];
    const float* z           = (const float*)d_in[1];
    const float* W           = (const float*)d_in[2];
    float*       out         = (float*)d_out;

    fused_decoder_kernel<<<GRID, 256>>>(init_states, z, W, out);
}